// round 1
// baseline (speedup 1.0000x reference)
#include <cuda_runtime.h>
#include <cstdint>

#define Bb 4
#define Hh 16
#define Ss 1024
#define Dd 128
#define BM 128
#define BN 64
#define NT (Ss/BN)
#define THREADS 256
#define TEMP 11.313708498984761f

#define SQ_LD 132
#define SK_LD 132
#define SV_LD 132
#define SS_LD 72

// total dynamic smem bytes
#define SMEM_BYTES ((BM*SQ_LD + BN*SK_LD + BN*SV_LD)*4 + BM*SS_LD*4)

__device__ __forceinline__ uint32_t f2tf(float f){
    uint32_t u; asm("cvt.rna.tf32.f32 %0, %1;" : "=r"(u) : "f"(f)); return u;
}

__device__ __forceinline__ void mma8(float* c, const uint32_t* a, const uint32_t* b){
    asm volatile(
        "mma.sync.aligned.m16n8k8.row.col.f32.tf32.tf32.f32 "
        "{%0,%1,%2,%3},{%4,%5,%6,%7},{%8,%9},{%0,%1,%2,%3};"
        : "+f"(c[0]), "+f"(c[1]), "+f"(c[2]), "+f"(c[3])
        : "r"(a[0]), "r"(a[1]), "r"(a[2]), "r"(a[3]), "r"(b[0]), "r"(b[1]));
}

extern __shared__ uint32_t smem_u[];

__global__ __launch_bounds__(THREADS, 1)
void sdpa_relu15_kernel(const float* __restrict__ q, const float* __restrict__ k,
                        const float* __restrict__ v, const int* __restrict__ mask,
                        float* __restrict__ out, float* __restrict__ attn)
{
    uint32_t* sQ = smem_u;                    // [BM][SQ_LD] tf32 (pre-scaled by 1/T)
    uint32_t* sK = sQ + BM*SQ_LD;             // [BN][SK_LD] tf32
    uint32_t* sV = sK + BN*SK_LD;             // [BN][SV_LD] tf32
    float*    sS = (float*)(sV + BN*SV_LD);   // [BM][SS_LD] fp32 clipped scores

    const int tid  = threadIdx.x;
    const int wid  = tid >> 5, lane = tid & 31;
    const int wm   = wid & 3,  wn   = wid >> 2;     // warp grid: 4 (m) x 2 (n/d)
    const int g    = lane >> 2, tg  = lane & 3;     // groupID, threadID_in_group
    const int bh   = blockIdx.y;
    const int q0   = blockIdx.x * BM;
    const size_t mbase = (size_t)(bh / Hh) * Ss * Ss;
    const float invT = 1.0f / TEMP;

    // ---- load Q tile (scaled, tf32) ----
    {
        const float4* qg = (const float4*)(q + (size_t)bh*Ss*Dd + (size_t)q0*Dd);
        #pragma unroll
        for (int i = 0; i < 16; i++) {
            int idx = tid + i*THREADS;            // 0..4095 float4s (128x128)
            int r = idx >> 5, c = (idx & 31) * 4;
            float4 t = qg[idx];
            uint32_t* d = sQ + r*SQ_LD + c;
            d[0]=f2tf(t.x*invT); d[1]=f2tf(t.y*invT); d[2]=f2tf(t.z*invT); d[3]=f2tf(t.w*invT);
        }
    }

    // O accumulator: per warp 32(m) x 64(d): 2 m16-tiles x 8 n8-tiles
    float o[16][4];
    #pragma unroll
    for (int i = 0; i < 16; i++) { o[i][0]=0.f; o[i][1]=0.f; o[i][2]=0.f; o[i][3]=0.f; }

    for (int nt = 0; nt < NT; nt++) {
        const int n0 = nt * BN;
        __syncthreads();   // previous iteration done with sK/sV/sS
        // ---- load K,V tiles (tf32) ----
        {
            const float4* kg = (const float4*)(k + (size_t)bh*Ss*Dd + (size_t)n0*Dd);
            const float4* vg = (const float4*)(v + (size_t)bh*Ss*Dd + (size_t)n0*Dd);
            #pragma unroll
            for (int i = 0; i < 8; i++) {
                int idx = tid + i*THREADS;        // 0..2047 float4s (64x128)
                int r = idx >> 5, c = (idx & 31) * 4;
                float4 t = kg[idx];
                uint32_t* dk = sK + r*SK_LD + c;
                dk[0]=f2tf(t.x); dk[1]=f2tf(t.y); dk[2]=f2tf(t.z); dk[3]=f2tf(t.w);
                float4 u = vg[idx];
                uint32_t* dv = sV + r*SV_LD + c;
                dv[0]=f2tf(u.x); dv[1]=f2tf(u.y); dv[2]=f2tf(u.z); dv[3]=f2tf(u.w);
            }
        }
        __syncthreads();

        // ---- GEMM1: S(128x64) = Qtile @ Ktile^T ; per warp 32x32 ----
        float sacc[8][4];
        #pragma unroll
        for (int i = 0; i < 8; i++) { sacc[i][0]=0.f; sacc[i][1]=0.f; sacc[i][2]=0.f; sacc[i][3]=0.f; }

        #pragma unroll
        for (int kk = 0; kk < 16; kk++) {
            uint32_t a[2][4];
            #pragma unroll
            for (int mi = 0; mi < 2; mi++) {
                int r = wm*32 + mi*16 + g;
                int c = kk*8 + tg;
                a[mi][0] = sQ[r*SQ_LD + c];
                a[mi][1] = sQ[(r+8)*SQ_LD + c];
                a[mi][2] = sQ[r*SQ_LD + c + 4];
                a[mi][3] = sQ[(r+8)*SQ_LD + c + 4];
            }
            #pragma unroll
            for (int ni = 0; ni < 4; ni++) {
                int n = wn*32 + ni*8 + g;
                int c = kk*8 + tg;
                uint32_t bf[2];
                bf[0] = sK[n*SK_LD + c];
                bf[1] = sK[n*SK_LD + c + 4];
                mma8(sacc[0*4 + ni], a[0], bf);
                mma8(sacc[1*4 + ni], a[1], bf);
            }
        }

        // ---- mask + clip, store to sS ----
        #pragma unroll
        for (int mi = 0; mi < 2; mi++) {
            #pragma unroll
            for (int ni = 0; ni < 4; ni++) {
                float* cc = sacc[mi*4 + ni];
                int r = wm*32 + mi*16 + g;
                int c = wn*32 + ni*8 + 2*tg;
                int2 m0 = *(const int2*)(mask + mbase + (size_t)(q0 + r    )*Ss + n0 + c);
                int2 m1 = *(const int2*)(mask + mbase + (size_t)(q0 + r + 8)*Ss + n0 + c);
                float v0 = m0.x ? fminf(fmaxf(cc[0], 0.f), 15.f) : 0.f;
                float v1 = m0.y ? fminf(fmaxf(cc[1], 0.f), 15.f) : 0.f;
                float v2 = m1.x ? fminf(fmaxf(cc[2], 0.f), 15.f) : 0.f;
                float v3 = m1.y ? fminf(fmaxf(cc[3], 0.f), 15.f) : 0.f;
                *(float2*)(sS + r*SS_LD + c)     = make_float2(v0, v1);
                *(float2*)(sS + (r+8)*SS_LD + c) = make_float2(v2, v3);
            }
        }
        __syncthreads();

        // ---- stream attn tile to gmem (coalesced float4) ----
        {
            float* ag = attn + (size_t)bh*Ss*Ss + (size_t)q0*Ss + n0;
            #pragma unroll
            for (int i = 0; i < 8; i++) {
                int idx = tid + i*THREADS;        // 0..2047 float4s (128x16)
                int r = idx >> 4, c = (idx & 15) * 4;
                float4 t = *(float4*)(sS + r*SS_LD + c);
                *(float4*)(ag + (size_t)r*Ss + c) = t;
            }
        }

        // ---- GEMM2: O(128x128) += S @ Vtile ; per warp 32(m) x 64(d) ----
        #pragma unroll
        for (int kk = 0; kk < 8; kk++) {
            uint32_t a[2][4];
            #pragma unroll
            for (int mi = 0; mi < 2; mi++) {
                int r = wm*32 + mi*16 + g;
                int c = kk*8 + tg;
                a[mi][0] = f2tf(sS[r*SS_LD + c]);
                a[mi][1] = f2tf(sS[(r+8)*SS_LD + c]);
                a[mi][2] = f2tf(sS[r*SS_LD + c + 4]);
                a[mi][3] = f2tf(sS[(r+8)*SS_LD + c + 4]);
            }
            #pragma unroll
            for (int di = 0; di < 8; di++) {
                int n = wn*64 + di*8 + g;          // d column
                int c = kk*8 + tg;                 // k row (within tile)
                uint32_t bf[2];
                bf[0] = sV[c*SV_LD + n];
                bf[1] = sV[(c+4)*SV_LD + n];
                mma8(o[0*8 + di], a[0], bf);
                mma8(o[1*8 + di], a[1], bf);
            }
        }
    }

    // ---- write O ----
    {
        float* og = out + (size_t)bh*Ss*Dd + (size_t)q0*Dd;
        #pragma unroll
        for (int mi = 0; mi < 2; mi++) {
            #pragma unroll
            for (int di = 0; di < 8; di++) {
                float* cc = o[mi*8 + di];
                int r = wm*32 + mi*16 + g;
                int c = wn*64 + di*8 + 2*tg;
                *(float2*)(og + (size_t)r*Dd + c)     = make_float2(cc[0], cc[1]);
                *(float2*)(og + (size_t)(r+8)*Dd + c) = make_float2(cc[2], cc[3]);
            }
        }
    }
}

extern "C" void kernel_launch(void* const* d_in, const int* in_sizes, int n_in,
                              void* d_out, int out_size)
{
    const float* q    = (const float*)d_in[0];
    const float* k    = (const float*)d_in[1];
    const float* v    = (const float*)d_in[2];
    const int*   mask = (const int*)  d_in[3];
    float* out  = (float*)d_out;
    float* attn = out + (size_t)Bb*Hh*Ss*Dd;   // tuple order: (out, attn)

    cudaFuncSetAttribute(sdpa_relu15_kernel,
                         cudaFuncAttributeMaxDynamicSharedMemorySize, SMEM_BYTES);

    dim3 grid(Ss/BM, Bb*Hh);
    sdpa_relu15_kernel<<<grid, THREADS, SMEM_BYTES>>>(q, k, v, mask, out, attn);
}

// round 3
// speedup vs baseline: 1.0494x; 1.0494x over previous
#include <cuda_runtime.h>
#include <cstdint>

#define Bb 4
#define Hh 16
#define Ss 1024
#define Dd 128
#define BM 128
#define BN 64
#define NT (Ss/BN)
#define THREADS 512
#define TEMP 11.313708498984761f

// ---- smem word-offsets (uint32 words) ----
// Q frag: [mb(8)][kk(16)][lane(32)][4], kk stride 132 words, mb stride 2112
#define OQ 0
#define Q_WORDS (8*2112)
// K frag: [nb(8)][kk(16)][lane(32)][2], kk stride 66, nb stride 1056
#define OK_ Q_WORDS                    // 16896
#define K_WORDS (8*1056)
// V row-major: [64 rows(k)][132], stride 132
#define OV (OK_ + K_WORDS)             // 25344
#define V_WORDS (64*132)
// sS row-major: [128][68]
#define OS (OV + V_WORDS)              // 33792
#define S_WORDS (128*68)
#define SMEM_WORDS (OS + S_WORDS)      // 42496
#define SMEM_BYTES (SMEM_WORDS*4)      // 169984

__device__ unsigned char g_flags[Bb*8*16];   // [b][qtile(8)][ktile(16)] all-ones flags

__device__ __forceinline__ uint32_t f2tf(float f){
    uint32_t u; asm("cvt.rna.tf32.f32 %0, %1;" : "=r"(u) : "f"(f)); return u;
}
__device__ __forceinline__ void mma8(float* c, uint32_t a0, uint32_t a1, uint32_t a2, uint32_t a3,
                                     uint32_t b0, uint32_t b1){
    asm volatile(
        "mma.sync.aligned.m16n8k8.row.col.f32.tf32.tf32.f32 "
        "{%0,%1,%2,%3},{%4,%5,%6,%7},{%8,%9},{%0,%1,%2,%3};"
        : "+f"(c[0]), "+f"(c[1]), "+f"(c[2]), "+f"(c[3])
        : "r"(a0), "r"(a1), "r"(a2), "r"(a3), "r"(b0), "r"(b1));
}

extern __shared__ uint32_t sm[];

// ---- pre-pass: per (b, qtile128, ktile64) all-ones mask flag ----
__global__ void mask_flags_kernel(const int* __restrict__ mask){
    const int kt = blockIdx.x, qt = blockIdx.y, b = blockIdx.z;
    const int* mb = mask + ((size_t)b*Ss + (size_t)qt*BM)*Ss + kt*BN;
    int ok = 1;
    #pragma unroll
    for (int i = 0; i < 8; i++) {
        int idx = threadIdx.x + i*256;          // 2048 int4s of [128][64]
        int r = idx >> 4, c = (idx & 15) * 4;
        int4 m = *(const int4*)(mb + (size_t)r*Ss + c);
        ok &= (m.x && m.y && m.z && m.w) ? 1 : 0;
    }
    ok = __syncthreads_and(ok);
    if (threadIdx.x == 0) g_flags[(b*8 + qt)*16 + kt] = (unsigned char)ok;
}

__global__ __launch_bounds__(THREADS)
void sdpa_relu15_v3(const float* __restrict__ q, const float* __restrict__ k,
                    const float* __restrict__ v, const int* __restrict__ mask,
                    float* __restrict__ out, float* __restrict__ attn)
{
    const int tid  = threadIdx.x;
    const int w    = tid >> 5, lane = tid & 31;
    const int wm   = w & 7, wn = w >> 3;          // 8 (m) x 2 (n/d) warp grid
    const int g    = lane >> 2, tg = lane & 3;
    const int bh   = blockIdx.y;
    const int q0   = blockIdx.x * BM;
    const int b    = bh >> 4;
    const size_t mbase = (size_t)b * Ss * Ss;
    const unsigned char* flags = &g_flags[(b*8 + blockIdx.x)*16];
    float* sSf = (float*)(sm + OS);

    // ---- Q -> fragment-major smem (scaled tf32), once ----
    {
        const float invT = 1.0f / TEMP;
        const float4* qg = (const float4*)(q + ((size_t)bh*Ss + q0)*Dd);
        #pragma unroll
        for (int i = 0; i < 8; i++) {
            int idx = tid + i*THREADS;            // 4096 float4s of [128][128]
            int r = idx >> 5, c4 = idx & 31;
            float4 t = qg[idx];
            uint32_t base = OQ + (r>>4)*2112 + (c4>>1)*132 + (r&7)*16
                          + (c4&1) + 2*((r>>3)&1);
            sm[base + 0] = f2tf(t.x*invT);
            sm[base + 4] = f2tf(t.y*invT);
            sm[base + 8] = f2tf(t.z*invT);
            sm[base +12] = f2tf(t.w*invT);
        }
    }

    const float* kb = k + (size_t)bh*Ss*Dd;
    const float* vb = v + (size_t)bh*Ss*Dd;
    float* ag_base = attn + (size_t)bh*Ss*Ss + (size_t)q0*Ss;

    // prefetch tile 0 into registers
    float4 kf[4], vf[4];
    {
        const float4* kg = (const float4*)kb;
        const float4* vg = (const float4*)vb;
        #pragma unroll
        for (int i = 0; i < 4; i++) { kf[i] = kg[tid + i*THREADS]; vf[i] = vg[tid + i*THREADS]; }
    }

    float o[8][4];
    #pragma unroll
    for (int i = 0; i < 8; i++) { o[i][0]=0.f; o[i][1]=0.f; o[i][2]=0.f; o[i][3]=0.f; }

    for (int nt = 0; nt < NT; nt++) {
        const int n0 = nt * BN;
        __syncthreads();   // prior tile's smem reads complete

        // ---- store prefetched K (frag-packed) and V (row-major) tiles ----
        #pragma unroll
        for (int i = 0; i < 4; i++) {
            int idx = tid + i*THREADS;            // 2048 float4s of [64][128]
            int r = idx >> 5, c4 = idx & 31;
            // K: value (n=r, k=4*c4+j)
            uint32_t kbase = OK_ + (r>>3)*1056 + (c4>>1)*66 + (r&7)*8 + (c4&1);
            sm[kbase + 0] = f2tf(kf[i].x);
            sm[kbase + 2] = f2tf(kf[i].y);
            sm[kbase + 4] = f2tf(kf[i].z);
            sm[kbase + 6] = f2tf(kf[i].w);
            // V: value (k=r, n=4*c4..)
            uint4 vv = make_uint4(f2tf(vf[i].x), f2tf(vf[i].y), f2tf(vf[i].z), f2tf(vf[i].w));
            *(uint4*)&sm[OV + r*132 + c4*4] = vv;
        }
        __syncthreads();

        // ---- issue next tile's global loads (latency hidden by GEMMs) ----
        if (nt < NT-1) {
            const float4* kg = (const float4*)(kb + (size_t)(n0+BN)*Dd);
            const float4* vg = (const float4*)(vb + (size_t)(n0+BN)*Dd);
            #pragma unroll
            for (int i = 0; i < 4; i++) { kf[i] = kg[tid + i*THREADS]; vf[i] = vg[tid + i*THREADS]; }
        }
        const unsigned char fl = flags[nt];

        // ---- GEMM1: S(128x64) = Q @ K^T ; warp: rows wm*16, cols wn*32 ----
        float sacc[4][4];
        #pragma unroll
        for (int i = 0; i < 4; i++) { sacc[i][0]=0.f; sacc[i][1]=0.f; sacc[i][2]=0.f; sacc[i][3]=0.f; }
        #pragma unroll
        for (int kk = 0; kk < 16; kk++) {
            uint4 aa = *(const uint4*)&sm[OQ + wm*2112 + kk*132 + lane*4];
            #pragma unroll
            for (int ni = 0; ni < 4; ni++) {
                uint2 bbv = *(const uint2*)&sm[OK_ + (wn*4+ni)*1056 + kk*66 + lane*2];
                mma8(sacc[ni], aa.x, aa.z, aa.y, aa.w, bbv.x, bbv.y);
            }
        }

        // ---- epilogue: mask + clip -> sS (row-major, stride 68) ----
        {
            const int r = wm*16 + g;
            #pragma unroll
            for (int ni = 0; ni < 4; ni++) {
                const int cc = wn*32 + ni*8 + 2*tg;
                float v0 = sacc[ni][0], v1 = sacc[ni][1], v2 = sacc[ni][2], v3 = sacc[ni][3];
                if (!fl) {
                    const int* mrow = mask + mbase + (size_t)(q0+r)*Ss + n0 + cc;
                    int2 m0 = *(const int2*)mrow;
                    int2 m1 = *(const int2*)(mrow + 8*Ss);
                    if (!m0.x) v0 = 0.f; if (!m0.y) v1 = 0.f;
                    if (!m1.x) v2 = 0.f; if (!m1.y) v3 = 0.f;
                }
                v0 = fminf(fmaxf(v0,0.f),15.f); v1 = fminf(fmaxf(v1,0.f),15.f);
                v2 = fminf(fmaxf(v2,0.f),15.f); v3 = fminf(fmaxf(v3,0.f),15.f);
                *(float2*)&sSf[r*68 + cc]     = make_float2(v0, v1);
                *(float2*)&sSf[(r+8)*68 + cc] = make_float2(v2, v3);
            }
        }
        __syncthreads();

        // ---- stream attn tile (coalesced) ----
        {
            float* ag = ag_base + n0;
            #pragma unroll
            for (int i = 0; i < 4; i++) {
                int idx = tid + i*THREADS;        // [128 rows][16 float4]
                int r = idx >> 4, c = (idx & 15) * 4;
                *(float4*)(ag + (size_t)r*Ss + c) = *(const float4*)&sSf[r*68 + c];
            }
        }

        // ---- GEMM2: O(128x128) += S @ V ; warp: rows wm*16, cols wn*64 ----
        #pragma unroll
        for (int kk = 0; kk < 8; kk++) {
            const float* srow = &sSf[(wm*16+g)*68 + kk*8 + tg];
            uint32_t a0 = f2tf(srow[0]);
            uint32_t a1 = f2tf(srow[8*68]);
            uint32_t a2 = f2tf(srow[4]);
            uint32_t a3 = f2tf(srow[8*68+4]);
            #pragma unroll
            for (int di = 0; di < 8; di++) {
                const int n = wn*64 + di*8 + g;
                uint32_t b0 = sm[OV + (kk*8+tg)*132 + n];
                uint32_t b1 = sm[OV + (kk*8+tg+4)*132 + n];
                mma8(o[di], a0, a1, a2, a3, b0, b1);
            }
        }
    }

    // ---- O writeout via sS staging (2 passes of 64 cols) ----
    float* og = out + ((size_t)bh*Ss + q0) * Dd;
    #pragma unroll
    for (int p = 0; p < 2; p++) {
        __syncthreads();
        if (wn == p) {
            const int r = wm*16 + g;
            #pragma unroll
            for (int di = 0; di < 8; di++) {
                const int cc = di*8 + 2*tg;
                *(float2*)&sSf[r*68 + cc]     = make_float2(o[di][0], o[di][1]);
                *(float2*)&sSf[(r+8)*68 + cc] = make_float2(o[di][2], o[di][3]);
            }
        }
        __syncthreads();
        #pragma unroll
        for (int i = 0; i < 4; i++) {
            int idx = tid + i*THREADS;            // [128 rows][16 float4]
            int r = idx >> 4, c = (idx & 15) * 4;
            *(float4*)(og + (size_t)r*Dd + p*64 + c) = *(const float4*)&sSf[r*68 + c];
        }
    }
}

extern "C" void kernel_launch(void* const* d_in, const int* in_sizes, int n_in,
                              void* d_out, int out_size)
{
    const float* q    = (const float*)d_in[0];
    const float* k    = (const float*)d_in[1];
    const float* v    = (const float*)d_in[2];
    const int*   mask = (const int*)  d_in[3];
    float* out  = (float*)d_out;
    float* attn = out + (size_t)Bb*Hh*Ss*Dd;   // tuple order: (out, attn)

    mask_flags_kernel<<<dim3(16, 8, Bb), 256>>>(mask);

    cudaFuncSetAttribute(sdpa_relu15_v3,
                         cudaFuncAttributeMaxDynamicSharedMemorySize, SMEM_BYTES);
    dim3 grid(Ss/BM, Bb*Hh);
    sdpa_relu15_v3<<<grid, THREADS, SMEM_BYTES>>>(q, k, v, mask, out, attn);
}

// round 4
// speedup vs baseline: 1.2994x; 1.2382x over previous
#include <cuda_runtime.h>
#include <cstdint>

#define Bb 4
#define Hh 16
#define Ss 1024
#define Dd 128
#define BM 128
#define BN 64
#define NT (Ss/BN)
#define THREADS 384
#define NCONS 256
#define TEMP 11.313708498984761f

// ---- smem word offsets ----
#define OQ 0
#define Q_WORDS (8*2112)          // 16896 : frag-major Q [mb8][kk16][lane32][4]
#define OK_ (OQ + Q_WORDS)        // 16896 : K row-major [64][132], single buffer
#define K_WORDS (64*132)
#define OV (OK_ + K_WORDS)        // 25344 : V row-major [64][132] x2 buffers
#define V_WORDS (64*132)
#define OS (OV + 2*V_WORDS)       // 42240 : sS row-major [128][68]
#define S_WORDS (128*68)
#define SMEM_WORDS (OS + S_WORDS) // 50944
#define SMEM_BYTES (SMEM_WORDS*4) // 203776

__device__ unsigned char g_flags[Bb*8*16];

__device__ __forceinline__ uint32_t f2tf(float f){
    uint32_t u; asm("cvt.rna.tf32.f32 %0, %1;" : "=r"(u) : "f"(f)); return u;
}
__device__ __forceinline__ uint32_t smem_u32(const void* p){
    uint32_t a; asm("{ .reg .u64 t; cvta.to.shared.u64 t, %1; cvt.u32.u64 %0, t; }" : "=r"(a) : "l"(p));
    return a;
}
__device__ __forceinline__ void mma8(float* c, uint32_t a0, uint32_t a1, uint32_t a2, uint32_t a3,
                                     uint32_t b0, uint32_t b1){
    asm volatile(
        "mma.sync.aligned.m16n8k8.row.col.f32.tf32.tf32.f32 "
        "{%0,%1,%2,%3},{%4,%5,%6,%7},{%8,%9},{%0,%1,%2,%3};"
        : "+f"(c[0]), "+f"(c[1]), "+f"(c[2]), "+f"(c[3])
        : "r"(a0), "r"(a1), "r"(a2), "r"(a3), "r"(b0), "r"(b1));
}
#define CP16(dst, src) asm volatile("cp.async.cg.shared.global [%0], [%1], 16;" :: "r"(dst), "l"(src) : "memory")
#define CP_COMMIT()    asm volatile("cp.async.commit_group;" ::: "memory")
#define CP_WAIT0()     asm volatile("cp.async.wait_group 0;" ::: "memory")

extern __shared__ uint32_t sm[];

// ---- pre-pass: per (b, qtile128, ktile64) all-ones mask flag ----
__global__ void mask_flags_kernel(const int* __restrict__ mask){
    const int kt = blockIdx.x, qt = blockIdx.y, b = blockIdx.z;
    const int* mb = mask + ((size_t)b*Ss + (size_t)qt*BM)*Ss + kt*BN;
    int ok = 1;
    #pragma unroll
    for (int i = 0; i < 8; i++) {
        int idx = threadIdx.x + i*256;
        int r = idx >> 4, c = (idx & 15) * 4;
        int4 m = *(const int4*)(mb + (size_t)r*Ss + c);
        ok &= (m.x && m.y && m.z && m.w) ? 1 : 0;
    }
    ok = __syncthreads_and(ok);
    if (threadIdx.x == 0) g_flags[(b*8 + qt)*16 + kt] = (unsigned char)ok;
}

__global__ __launch_bounds__(THREADS, 1)
void sdpa_relu15_v4(const float* __restrict__ q, const float* __restrict__ k,
                    const float* __restrict__ v, const int* __restrict__ mask,
                    float* __restrict__ out, float* __restrict__ attn)
{
    const int tid  = threadIdx.x;
    const int lane = tid & 31;
    const int g    = lane >> 2, tg = lane & 3;
    const int bh   = blockIdx.y;
    const int q0   = blockIdx.x * BM;
    const int b    = bh >> 4;
    const size_t mbase = (size_t)b * Ss * Ss;
    const unsigned char* flags = &g_flags[(b*8 + blockIdx.x)*16];
    float* smf = (float*)sm;
    float* sSf = smf + OS;
    const uint32_t sbase = smem_u32(sm);

    const float* kb = k + (size_t)bh*Ss*Dd;
    const float* vb = v + (size_t)bh*Ss*Dd;
    float* ag_base = attn + (size_t)bh*Ss*Ss + (size_t)q0*Ss;

    // ---- prologue: Q -> fragment-major smem (all threads) ----
    {
        const float invT = 1.0f / TEMP;
        const float4* qg = (const float4*)(q + ((size_t)bh*Ss + q0)*Dd);
        #pragma unroll
        for (int i = 0; i < 11; i++) {
            int idx = tid + i*THREADS;
            if (idx < 4096) {
                int r = idx >> 5, c4 = idx & 31;
                float4 t = qg[idx];
                uint32_t base = OQ + (r>>4)*2112 + (c4>>1)*132 + (r&7)*16
                              + (c4&1) + 2*((r>>3)&1);
                sm[base + 0] = f2tf(t.x*invT);
                sm[base + 4] = f2tf(t.y*invT);
                sm[base + 8] = f2tf(t.z*invT);
                sm[base +12] = f2tf(t.w*invT);
            }
        }
    }
    // producers prefetch tile 0
    if (tid >= NCONS) {
        const int pt = tid - NCONS;       // 0..127
        #pragma unroll
        for (int i = 0; i < 16; i++) {
            int c = pt + i*128;           // 2048 chunks of [64][32]
            int r = c >> 5, c16 = c & 31;
            CP16(sbase + (OK_ + r*132 + c16*4)*4, kb + r*128 + c16*4);
            CP16(sbase + (OV  + r*132 + c16*4)*4, vb + r*128 + c16*4);
        }
        CP_COMMIT(); CP_WAIT0();
    }
    __syncthreads();

    float o[2][8][4];
    #pragma unroll
    for (int mi = 0; mi < 2; mi++)
        #pragma unroll
        for (int di = 0; di < 8; di++)
            { o[mi][di][0]=0.f; o[mi][di][1]=0.f; o[mi][di][2]=0.f; o[mi][di][3]=0.f; }

    const int w  = tid >> 5;
    const int wm = w & 3, wn = (w >> 2) & 1;   // consumers: 4(m) x 2(n)

    for (int nt = 0; nt < NT; nt++) {
        const int n0 = nt * BN;
        const int vo = OV + (nt & 1) * V_WORDS;

        if (tid < NCONS) {
            // ================= consumers =================
            // GEMM1: S(128x64) = Q @ K^T ; warp tile 32x32
            float sacc[2][4][4];
            #pragma unroll
            for (int mi = 0; mi < 2; mi++)
                #pragma unroll
                for (int ni = 0; ni < 4; ni++)
                    { sacc[mi][ni][0]=0.f; sacc[mi][ni][1]=0.f; sacc[mi][ni][2]=0.f; sacc[mi][ni][3]=0.f; }
            #pragma unroll
            for (int kk = 0; kk < 16; kk++) {
                uint4 aa0 = *(const uint4*)&sm[OQ + (2*wm  )*2112 + kk*132 + lane*4];
                uint4 aa1 = *(const uint4*)&sm[OQ + (2*wm+1)*2112 + kk*132 + lane*4];
                #pragma unroll
                for (int ni = 0; ni < 4; ni++) {
                    int n = wn*32 + ni*8 + g;
                    uint32_t b0 = f2tf(smf[OK_ + n*132 + kk*8 + tg]);
                    uint32_t b1 = f2tf(smf[OK_ + n*132 + kk*8 + tg + 4]);
                    mma8(sacc[0][ni], aa0.x, aa0.z, aa0.y, aa0.w, b0, b1);
                    mma8(sacc[1][ni], aa1.x, aa1.z, aa1.y, aa1.w, b0, b1);
                }
            }
            // epilogue: mask + clip -> sS row-major
            const unsigned char fl = flags[nt];
            #pragma unroll
            for (int mi = 0; mi < 2; mi++) {
                const int r = wm*32 + mi*16 + g;
                #pragma unroll
                for (int ni = 0; ni < 4; ni++) {
                    const int cc = wn*32 + ni*8 + 2*tg;
                    float* s4 = sacc[mi][ni];
                    float v0 = s4[0], v1 = s4[1], v2 = s4[2], v3 = s4[3];
                    if (!fl) {
                        const int* mrow = mask + mbase + (size_t)(q0+r)*Ss + n0 + cc;
                        int2 m0 = *(const int2*)mrow;
                        int2 m1 = *(const int2*)(mrow + 8*Ss);
                        if (!m0.x) v0 = 0.f; if (!m0.y) v1 = 0.f;
                        if (!m1.x) v2 = 0.f; if (!m1.y) v3 = 0.f;
                    }
                    v0 = fminf(fmaxf(v0,0.f),15.f); v1 = fminf(fmaxf(v1,0.f),15.f);
                    v2 = fminf(fmaxf(v2,0.f),15.f); v3 = fminf(fmaxf(v3,0.f),15.f);
                    *(float2*)&sSf[r*68 + cc]     = make_float2(v0, v1);
                    *(float2*)&sSf[(r+8)*68 + cc] = make_float2(v2, v3);
                }
            }
            __syncthreads();   // S ready; GEMM1 done -> K buffer free

            // GEMM2: O(128x128) += S @ V ; warp tile 32(m) x 64(d)
            #pragma unroll
            for (int kk = 0; kk < 8; kk++) {
                uint32_t a[2][4];
                #pragma unroll
                for (int mi = 0; mi < 2; mi++) {
                    const float* srow = &sSf[(wm*32 + mi*16 + g)*68 + kk*8 + tg];
                    a[mi][0] = f2tf(srow[0]);
                    a[mi][1] = f2tf(srow[8*68]);
                    a[mi][2] = f2tf(srow[4]);
                    a[mi][3] = f2tf(srow[8*68 + 4]);
                }
                #pragma unroll
                for (int di = 0; di < 8; di++) {
                    const int n = wn*64 + di*8 + g;
                    uint32_t b0 = f2tf(smf[vo + (kk*8+tg  )*132 + n]);
                    uint32_t b1 = f2tf(smf[vo + (kk*8+tg+4)*132 + n]);
                    mma8(o[0][di], a[0][0], a[0][1], a[0][2], a[0][3], b0, b1);
                    mma8(o[1][di], a[1][0], a[1][1], a[1][2], a[1][3], b0, b1);
                }
            }
            __syncthreads();   // GEMM2 done -> V buffer free; attn done
        } else {
            // ================= producers =================
            const int pt = tid - NCONS;   // 0..127
            if (nt < NT-1) {
                const float* vp = vb + (size_t)(n0+BN)*Dd;
                const int vn = OV + ((nt+1) & 1) * V_WORDS;
                #pragma unroll
                for (int i = 0; i < 16; i++) {
                    int c = pt + i*128;
                    int r = c >> 5, c16 = c & 31;
                    CP16(sbase + (vn + r*132 + c16*4)*4, vp + r*128 + c16*4);
                }
                CP_COMMIT();
            }
            __syncthreads();   // wait S ready / K free
            if (nt < NT-1) {
                const float* kp = kb + (size_t)(n0+BN)*Dd;
                #pragma unroll
                for (int i = 0; i < 16; i++) {
                    int c = pt + i*128;
                    int r = c >> 5, c16 = c & 31;
                    CP16(sbase + (OK_ + r*132 + c16*4)*4, kp + r*128 + c16*4);
                }
                CP_COMMIT();
                CP_WAIT0();    // V(nt+1) and K(nt+1) both arrived
            }
            // stream attn tile from sS (off compute critical path)
            float* ag = ag_base + n0;
            #pragma unroll
            for (int i = 0; i < 16; i++) {
                int idx = pt + i*128;      // [128 rows][16 float4]
                int r = idx >> 4, c = (idx & 15) * 4;
                *(float4*)(ag + (size_t)r*Ss + c) = *(const float4*)&sSf[r*68 + c];
            }
            __syncthreads();
        }
    }

    // ---- O writeout via sS staging ----
    float* og = out + ((size_t)bh*Ss + q0) * Dd;
    #pragma unroll
    for (int p = 0; p < 2; p++) {
        if (tid < NCONS && wn == p) {
            #pragma unroll
            for (int mi = 0; mi < 2; mi++) {
                const int r = wm*32 + mi*16 + g;
                #pragma unroll
                for (int di = 0; di < 8; di++) {
                    const int cc = di*8 + 2*tg;
                    *(float2*)&sSf[r*68 + cc]     = make_float2(o[mi][di][0], o[mi][di][1]);
                    *(float2*)&sSf[(r+8)*68 + cc] = make_float2(o[mi][di][2], o[mi][di][3]);
                }
            }
        }
        __syncthreads();
        #pragma unroll
        for (int i = 0; i < 6; i++) {
            int idx = tid + i*THREADS;
            if (idx < 2048) {
                int r = idx >> 4, c = (idx & 15) * 4;
                *(float4*)(og + (size_t)r*Dd + p*64 + c) = *(const float4*)&sSf[r*68 + c];
            }
        }
        __syncthreads();
    }
}

extern "C" void kernel_launch(void* const* d_in, const int* in_sizes, int n_in,
                              void* d_out, int out_size)
{
    const float* q    = (const float*)d_in[0];
    const float* k    = (const float*)d_in[1];
    const float* v    = (const float*)d_in[2];
    const int*   mask = (const int*)  d_in[3];
    float* out  = (float*)d_out;
    float* attn = out + (size_t)Bb*Hh*Ss*Dd;

    mask_flags_kernel<<<dim3(16, 8, Bb), 256>>>(mask);

    cudaFuncSetAttribute(sdpa_relu15_v4,
                         cudaFuncAttributeMaxDynamicSharedMemorySize, SMEM_BYTES);
    dim3 grid(Ss/BM, Bb*Hh);
    sdpa_relu15_v4<<<grid, THREADS, SMEM_BYTES>>>(q, k, v, mask, out, attn);
}